// round 7
// baseline (speedup 1.0000x reference)
#include <cuda_runtime.h>
#include <cuda_fp16.h>
#include <math.h>
#include <stdint.h>

// Problem sizes (fixed)
#define M_TOTAL 32768
#define K_TOTAL 2048
#define N_TOTAL 2048

// Work-unit tiling
#define BM 128
#define BN 64
#define BK 64
#define NKI   (K_TOTAL / BK)     // 32 k-iters per unit
#define NTILES (N_TOTAL / BN)    // 32 n-tiles per panel
#define PANELS (M_TOTAL / BM)    // 256 panels
#define UNITS  (PANELS * NTILES) // 8192 units
#define THREADS 256              // 8 warps: 4 (M) x 2 (N); warp tile 32x32
#define GRID 296                 // 2 CTAs per SM

// SMEM stage layout: xs (128x64 f16 = 16KB) + ws (64x64 f16 = 8KB)
#define XS_BYTES 16384
#define STAGE_BYTES 24576
#define NSTAGE 3
#define COMB_OFF (NSTAGE * STAGE_BYTES)          // 73728
#define SMEM_TOTAL (COMB_OFF + 2 * 128 * 8)      // +2KB comb = 75776

// fp16 scratch + LSE partials
__device__ __half g_x16[(size_t)M_TOTAL * K_TOTAL];    // 128 MB (M,K)
__device__ __half g_wt16[(size_t)N_TOTAL * K_TOTAL];   //   8 MB (N,K) = W^T
__device__ float2 g_part[NTILES][M_TOTAL];             //   8 MB partial (m,s)

// ---------------- conversion kernels ---------------------------------------
__global__ void conv_x_kernel(const float* __restrict__ src) {
    size_t i = (size_t)blockIdx.x * blockDim.x + threadIdx.x;   // float4 index
    float4 v = reinterpret_cast<const float4*>(src)[i];
    __half2 h0 = __floats2half2_rn(v.x, v.y);
    __half2 h1 = __floats2half2_rn(v.z, v.w);
    uint2 o;
    o.x = *reinterpret_cast<unsigned*>(&h0);
    o.y = *reinterpret_cast<unsigned*>(&h1);
    reinterpret_cast<uint2*>(g_x16)[i] = o;
}

// W (K,N) f32 -> Wt (N,K) f16 via 32x32 smem tile transpose
__global__ void conv_wt_kernel(const float* __restrict__ W) {
    __shared__ float t[32][33];
    int n0 = blockIdx.x * 32, k0 = blockIdx.y * 32;
    int tx = threadIdx.x, ty = threadIdx.y;   // 32 x 8
    #pragma unroll
    for (int j = 0; j < 4; ++j)
        t[ty + j * 8][tx] = W[(size_t)(k0 + ty + j * 8) * N_TOTAL + n0 + tx];
    __syncthreads();
    #pragma unroll
    for (int j = 0; j < 4; ++j)
        g_wt16[(size_t)(n0 + ty + j * 8) * K_TOTAL + k0 + tx] =
            __float2half(t[tx][ty + j * 8]);
}

// ---------------- helpers ---------------------------------------------------
__device__ __forceinline__ uint32_t smem_u32(const void* p) {
    return (uint32_t)__cvta_generic_to_shared(p);
}
__device__ __forceinline__ void cp_async16(uint32_t dst, const void* src) {
    asm volatile("cp.async.cg.shared.global [%0], [%1], 16;\n" :: "r"(dst), "l"(src));
}
__device__ __forceinline__ uint32_t sw128(uint32_t off) {   // SW128 xor swizzle
    return off ^ ((off >> 3) & 0x70);
}

// Fill one stage: x 1024 chunks (4/thr) + Wt 512 chunks (2/thr), 16B each
__device__ __forceinline__ void load_stage(uint32_t st, int tid,
                                           int r0, int n0, int kk) {
    #pragma unroll
    for (int i = 0; i < 4; ++i) {
        int c = tid + i * THREADS;
        int row = c >> 3, c16 = c & 7;
        cp_async16(st + sw128(row * 128 + c16 * 16),
                   g_x16 + (size_t)(r0 + row) * K_TOTAL + kk + c16 * 8);
    }
    #pragma unroll
    for (int i = 0; i < 2; ++i) {
        int c = tid + i * THREADS;
        int row = c >> 3, c16 = c & 7;
        cp_async16(st + XS_BYTES + sw128(row * 128 + c16 * 16),
                   g_wt16 + (size_t)(n0 + row) * K_TOTAL + kk + c16 * 8);
    }
}

// ---------------- persistent fused GEMM + per-unit LSE partial --------------
// Hybrid accumulation: fp16 accumulators within one BK=64 chunk (2x HMMA rate),
// widened and folded into persistent fp32 accumulators once per chunk.
__global__ __launch_bounds__(THREADS, 2)
void gemm_lse_kernel(const float* __restrict__ bias)
{
    extern __shared__ __align__(1024) char smem[];
    const uint32_t sb = smem_u32(smem);
    float2* comb = reinterpret_cast<float2*>(smem + COMB_OFF);   // [2][128]

    const int tid  = threadIdx.x;
    const int lane = tid & 31;
    const int wid  = tid >> 5;
    const int wm   = wid >> 1;          // 0..3 : 32-row slab
    const int wn   = wid & 1;           // 0..1 : 32-col slab
    const int qr   = lane >> 2;         // 0..7
    const int qc   = lane & 3;          // 0..3

    // ldmatrix lane addressing (shared by A and B tiles, both K-major 128B rows)
    const int lm_row = lane & 15;
    const int lm_c16 = (lane >> 4) * 16;   // byte offset of 8-half chunk

    for (int u = blockIdx.x; u < UNITS; u += GRID) {
        const int p  = u >> 5;          // panel
        const int nt = u & 31;          // n-tile
        const int r0 = p * BM;
        const int n0 = nt * BN;

        float acc[2][4][4];
        #pragma unroll
        for (int mi = 0; mi < 2; ++mi)
            #pragma unroll
            for (int j = 0; j < 4; ++j)
                #pragma unroll
                for (int c = 0; c < 4; ++c) acc[mi][j][c] = 0.0f;

        // prologue: stages 0,1
        load_stage(sb + 0 * STAGE_BYTES, tid, r0, n0, 0);
        asm volatile("cp.async.commit_group;\n");
        load_stage(sb + 1 * STAGE_BYTES, tid, r0, n0, BK);
        asm volatile("cp.async.commit_group;\n");

        for (int kt = 0; kt < NKI; ++kt) {
            asm volatile("cp.async.wait_group 1;\n");
            __syncthreads();

            if (kt + 2 < NKI)
                load_stage(sb + ((kt + 2) % NSTAGE) * STAGE_BYTES, tid,
                           r0, n0, (kt + 2) * BK);
            asm volatile("cp.async.commit_group;\n");

            const uint32_t st = sb + (kt % NSTAGE) * STAGE_BYTES;

            // fp16 chunk accumulators: [mi][j] x 2 b32 regs (4 halves)
            unsigned cf[2][4][2];
            #pragma unroll
            for (int mi = 0; mi < 2; ++mi)
                #pragma unroll
                for (int j = 0; j < 4; ++j)
                    cf[mi][j][0] = cf[mi][j][1] = 0u;

            #pragma unroll
            for (int ks = 0; ks < 4; ++ks) {
                unsigned a[2][4];
                #pragma unroll
                for (int mi = 0; mi < 2; ++mi) {
                    uint32_t addr = st + sw128(
                        (wm * 32 + mi * 16 + lm_row) * 128 + ks * 32 + lm_c16);
                    asm volatile(
                        "ldmatrix.sync.aligned.m8n8.x4.shared.b16 {%0,%1,%2,%3}, [%4];\n"
                        : "=r"(a[mi][0]), "=r"(a[mi][1]), "=r"(a[mi][2]), "=r"(a[mi][3])
                        : "r"(addr));
                }
                unsigned b[2][4];
                #pragma unroll
                for (int nb = 0; nb < 2; ++nb) {
                    uint32_t addr = st + XS_BYTES + sw128(
                        (wn * 32 + nb * 16 + lm_row) * 128 + ks * 32 + lm_c16);
                    asm volatile(
                        "ldmatrix.sync.aligned.m8n8.x4.shared.b16 {%0,%1,%2,%3}, [%4];\n"
                        : "=r"(b[nb][0]), "=r"(b[nb][1]), "=r"(b[nb][2]), "=r"(b[nb][3])
                        : "r"(addr));
                }
                #pragma unroll
                for (int mi = 0; mi < 2; ++mi)
                    #pragma unroll
                    for (int j = 0; j < 4; ++j) {
                        unsigned b0 = b[j >> 1][(j & 1)];
                        unsigned b1 = b[j >> 1][(j & 1) + 2];
                        asm volatile(
                            "mma.sync.aligned.m16n8k16.row.col.f16.f16.f16.f16 "
                            "{%0,%1}, {%2,%3,%4,%5}, {%6,%7}, {%0,%1};\n"
                            : "+r"(cf[mi][j][0]), "+r"(cf[mi][j][1])
                            : "r"(a[mi][0]), "r"(a[mi][1]), "r"(a[mi][2]), "r"(a[mi][3]),
                              "r"(b0), "r"(b1));
                    }
            }

            // widen chunk result and fold into fp32 accumulators
            #pragma unroll
            for (int mi = 0; mi < 2; ++mi)
                #pragma unroll
                for (int j = 0; j < 4; ++j) {
                    float2 lo = __half22float2(
                        *reinterpret_cast<__half2*>(&cf[mi][j][0]));
                    float2 hi = __half22float2(
                        *reinterpret_cast<__half2*>(&cf[mi][j][1]));
                    acc[mi][j][0] += lo.x;
                    acc[mi][j][1] += lo.y;
                    acc[mi][j][2] += hi.x;
                    acc[mi][j][3] += hi.y;
                }
        }

        // ---- per-unit LSE partial: thread cols = n0 + wn*32 + j*8 + qc*2 ----
        float2 bj[4];
        {
            const float2* bb = reinterpret_cast<const float2*>(
                bias + n0 + wn * 32) + qc;
            #pragma unroll
            for (int j = 0; j < 4; ++j) bj[j] = __ldg(&bb[j * 4]);
        }
        float tile_m[2][2], tile_s[2][2];
        #pragma unroll
        for (int mi = 0; mi < 2; ++mi)
            #pragma unroll
            for (int h = 0; h < 2; ++h) {
                float v[8];
                #pragma unroll
                for (int j = 0; j < 4; ++j) {
                    v[j * 2]     = acc[mi][j][h * 2]     + bj[j].x;
                    v[j * 2 + 1] = acc[mi][j][h * 2 + 1] + bj[j].y;
                }
                float tm = v[0];
                #pragma unroll
                for (int c = 1; c < 8; ++c) tm = fmaxf(tm, v[c]);
                tm = fmaxf(tm, __shfl_xor_sync(0xFFFFFFFFu, tm, 1));
                tm = fmaxf(tm, __shfl_xor_sync(0xFFFFFFFFu, tm, 2));
                float s = 0.0f;
                #pragma unroll
                for (int c = 0; c < 8; ++c) s += __expf(v[c] - tm);
                s += __shfl_xor_sync(0xFFFFFFFFu, s, 1);
                s += __shfl_xor_sync(0xFFFFFFFFu, s, 2);
                tile_m[mi][h] = tm;
                tile_s[mi][h] = s;
            }

        __syncthreads();   // mainloop smem reads done in all warps
        if (qc == 0) {
            #pragma unroll
            for (int mi = 0; mi < 2; ++mi)
                #pragma unroll
                for (int h = 0; h < 2; ++h) {
                    int row = wm * 32 + mi * 16 + h * 8 + qr;
                    comb[wn * 128 + row] =
                        make_float2(tile_m[mi][h], tile_s[mi][h]);
                }
        }
        __syncthreads();
        if (tid < BM) {
            float2 p0 = comb[tid];
            float2 p1 = comb[128 + tid];
            float nm = fmaxf(p0.x, p1.x);
            float s  = p0.y * __expf(p0.x - nm) + p1.y * __expf(p1.x - nm);
            g_part[nt][r0 + tid] = make_float2(nm, s);
        }
    }
}

// ---------------- final combine: 32 partials per row + activation chain ----
__global__ void combine_kernel(float* __restrict__ out) {
    int r = blockIdx.x * 256 + threadIdx.x;
    float m = -INFINITY, s = 0.0f;
    #pragma unroll 4
    for (int nt = 0; nt < NTILES; ++nt) {
        float2 p = g_part[nt][r];
        float nm = fmaxf(m, p.x);
        s = s * __expf(m - nm) + p.y * __expf(p.x - nm);
        m = nm;
    }
    float z = m + logf(s);
    z = (z > 0.0f) ? z : 0.01f * z;
    z = (z > 0.0f) ? z : 0.01f * z;
    z = 0.5f * z * (1.0f + erff(z * 0.70710678118654752f));
    z = 0.5f * z * (1.0f + erff(z * 0.70710678118654752f));
    out[r] = z;
}

extern "C" void kernel_launch(void* const* d_in, const int* in_sizes, int n_in,
                              void* d_out, int out_size)
{
    const float* x    = (const float*)d_in[0];   // (M, K) f32 (widened fp16)
    const float* W    = (const float*)d_in[1];   // (K, N) f32
    const float* bias = (const float*)d_in[2];   // (N,)   f32
    float* out        = (float*)d_out;           // (M, 1) f32

    cudaFuncSetAttribute(gemm_lse_kernel,
                         cudaFuncAttributeMaxDynamicSharedMemorySize, SMEM_TOTAL);

    conv_x_kernel<<<(M_TOTAL * (size_t)K_TOTAL / 4) / 256, 256>>>(x);
    conv_wt_kernel<<<dim3(N_TOTAL / 32, K_TOTAL / 32), dim3(32, 8)>>>(W);
    gemm_lse_kernel<<<GRID, THREADS, SMEM_TOTAL>>>(bias);
    combine_kernel<<<M_TOTAL / 256, 256>>>(out);
}

// round 8
// speedup vs baseline: 1.2087x; 1.2087x over previous
#include <cuda_runtime.h>
#include <cuda_fp16.h>
#include <math.h>
#include <stdint.h>

// Problem sizes (fixed)
#define M_TOTAL 32768
#define K_TOTAL 2048
#define N_TOTAL 2048

// Work-unit tiling
#define BM 128
#define BN 128
#define BK 64
#define NKI    (K_TOTAL / BK)    // 32 k-iters per unit
#define NTILES (N_TOTAL / BN)    // 16 n-tiles per panel
#define PANELS (M_TOTAL / BM)    // 256 panels
#define UNITS  (PANELS * NTILES) // 4096 units
#define THREADS 256              // 8 warps: 4 (M) x 2 (N); warp tile 32x64
#define GRID 296                 // 2 CTAs per SM

// SMEM stage layout: xs (128x64 f16 = 16KB) + ws (128x64 f16 = 16KB)
#define XS_BYTES 16384
#define STAGE_BYTES 32768
#define NSTAGE 3
#define COMB_OFF (NSTAGE * STAGE_BYTES)          // 98304
#define SMEM_TOTAL (COMB_OFF + 2 * 128 * 8)      // +2KB comb = 100352

// fp16 scratch + LSE partials
__device__ __half g_x16[(size_t)M_TOTAL * K_TOTAL];    // 128 MB (M,K)
__device__ __half g_wt16[(size_t)N_TOTAL * K_TOTAL];   //   8 MB (N,K) = W^T
__device__ float2 g_part[NTILES][M_TOTAL];             //   4 MB partial (m,s)

// ---------------- conversion kernels ---------------------------------------
__global__ void conv_x_kernel(const float* __restrict__ src) {
    size_t i = (size_t)blockIdx.x * blockDim.x + threadIdx.x;   // float4 index
    float4 v = reinterpret_cast<const float4*>(src)[i];
    __half2 h0 = __floats2half2_rn(v.x, v.y);
    __half2 h1 = __floats2half2_rn(v.z, v.w);
    uint2 o;
    o.x = *reinterpret_cast<unsigned*>(&h0);
    o.y = *reinterpret_cast<unsigned*>(&h1);
    reinterpret_cast<uint2*>(g_x16)[i] = o;
}

// W (K,N) f32 -> Wt (N,K) f16 via 32x32 smem tile transpose
__global__ void conv_wt_kernel(const float* __restrict__ W) {
    __shared__ float t[32][33];
    int n0 = blockIdx.x * 32, k0 = blockIdx.y * 32;
    int tx = threadIdx.x, ty = threadIdx.y;   // 32 x 8
    #pragma unroll
    for (int j = 0; j < 4; ++j)
        t[ty + j * 8][tx] = W[(size_t)(k0 + ty + j * 8) * N_TOTAL + n0 + tx];
    __syncthreads();
    #pragma unroll
    for (int j = 0; j < 4; ++j)
        g_wt16[(size_t)(n0 + ty + j * 8) * K_TOTAL + k0 + tx] =
            __float2half(t[tx][ty + j * 8]);
}

// ---------------- helpers ---------------------------------------------------
__device__ __forceinline__ uint32_t smem_u32(const void* p) {
    return (uint32_t)__cvta_generic_to_shared(p);
}
__device__ __forceinline__ void cp_async16(uint32_t dst, const void* src) {
    asm volatile("cp.async.cg.shared.global [%0], [%1], 16;\n" :: "r"(dst), "l"(src));
}
__device__ __forceinline__ uint32_t sw128(uint32_t off) {   // SW128 xor swizzle
    return off ^ ((off >> 3) & 0x70);
}

// Fill one stage: x 1024 chunks (4/thr) + Wt 1024 chunks (4/thr), 16B each
__device__ __forceinline__ void load_stage(uint32_t st, int tid,
                                           int r0, int n0, int kk) {
    #pragma unroll
    for (int i = 0; i < 4; ++i) {
        int c = tid + i * THREADS;
        int row = c >> 3, c16 = c & 7;
        cp_async16(st + sw128(row * 128 + c16 * 16),
                   g_x16 + (size_t)(r0 + row) * K_TOTAL + kk + c16 * 8);
    }
    #pragma unroll
    for (int i = 0; i < 4; ++i) {
        int c = tid + i * THREADS;
        int row = c >> 3, c16 = c & 7;
        cp_async16(st + XS_BYTES + sw128(row * 128 + c16 * 16),
                   g_wt16 + (size_t)(n0 + row) * K_TOTAL + kk + c16 * 8);
    }
}

// ---------------- persistent fused GEMM + per-unit LSE partial --------------
__global__ __launch_bounds__(THREADS, 2)
void gemm_lse_kernel(const float* __restrict__ bias)
{
    extern __shared__ __align__(1024) char smem[];
    const uint32_t sb = smem_u32(smem);
    float2* comb = reinterpret_cast<float2*>(smem + COMB_OFF);   // [2][128]

    const int tid  = threadIdx.x;
    const int lane = tid & 31;
    const int wid  = tid >> 5;
    const int wm   = wid >> 1;          // 0..3 : 32-row slab
    const int wn   = wid & 1;           // 0..1 : 64-col slab
    const int qr   = lane >> 2;         // 0..7
    const int qc   = lane & 3;          // 0..3

    // ldmatrix lane addressing (A and B tiles, both K-major 128B rows)
    const int lm_row = lane & 15;
    const int lm_c16 = (lane >> 4) * 16;   // byte offset of 8-half chunk

    for (int u = blockIdx.x; u < UNITS; u += GRID) {
        const int p  = u >> 4;          // panel
        const int nt = u & 15;          // n-tile
        const int r0 = p * BM;
        const int n0 = nt * BN;

        float acc[2][8][4];
        #pragma unroll
        for (int mi = 0; mi < 2; ++mi)
            #pragma unroll
            for (int j = 0; j < 8; ++j)
                #pragma unroll
                for (int c = 0; c < 4; ++c) acc[mi][j][c] = 0.0f;

        // prologue: stages 0,1
        load_stage(sb + 0 * STAGE_BYTES, tid, r0, n0, 0);
        asm volatile("cp.async.commit_group;\n");
        load_stage(sb + 1 * STAGE_BYTES, tid, r0, n0, BK);
        asm volatile("cp.async.commit_group;\n");

        for (int kt = 0; kt < NKI; ++kt) {
            asm volatile("cp.async.wait_group 1;\n");
            __syncthreads();

            if (kt + 2 < NKI)
                load_stage(sb + ((kt + 2) % NSTAGE) * STAGE_BYTES, tid,
                           r0, n0, (kt + 2) * BK);
            asm volatile("cp.async.commit_group;\n");

            const uint32_t st = sb + (kt % NSTAGE) * STAGE_BYTES;

            #pragma unroll
            for (int ks = 0; ks < 4; ++ks) {
                unsigned a[2][4];
                #pragma unroll
                for (int mi = 0; mi < 2; ++mi) {
                    uint32_t addr = st + sw128(
                        (wm * 32 + mi * 16 + lm_row) * 128 + ks * 32 + lm_c16);
                    asm volatile(
                        "ldmatrix.sync.aligned.m8n8.x4.shared.b16 {%0,%1,%2,%3}, [%4];\n"
                        : "=r"(a[mi][0]), "=r"(a[mi][1]), "=r"(a[mi][2]), "=r"(a[mi][3])
                        : "r"(addr));
                }
                unsigned b[4][4];
                #pragma unroll
                for (int nb = 0; nb < 4; ++nb) {
                    uint32_t addr = st + XS_BYTES + sw128(
                        (wn * 64 + nb * 16 + lm_row) * 128 + ks * 32 + lm_c16);
                    asm volatile(
                        "ldmatrix.sync.aligned.m8n8.x4.shared.b16 {%0,%1,%2,%3}, [%4];\n"
                        : "=r"(b[nb][0]), "=r"(b[nb][1]), "=r"(b[nb][2]), "=r"(b[nb][3])
                        : "r"(addr));
                }
                #pragma unroll
                for (int mi = 0; mi < 2; ++mi)
                    #pragma unroll
                    for (int j = 0; j < 8; ++j) {
                        // n-group j*8: 16-col block nb=j>>1; (j&1): low/high 8 cols
                        unsigned b0 = b[j >> 1][(j & 1)];
                        unsigned b1 = b[j >> 1][(j & 1) + 2];
                        asm volatile(
                            "mma.sync.aligned.m16n8k16.row.col.f32.f16.f16.f32 "
                            "{%0,%1,%2,%3}, {%4,%5,%6,%7}, {%8,%9}, {%0,%1,%2,%3};\n"
                            : "+f"(acc[mi][j][0]), "+f"(acc[mi][j][1]),
                              "+f"(acc[mi][j][2]), "+f"(acc[mi][j][3])
                            : "r"(a[mi][0]), "r"(a[mi][1]), "r"(a[mi][2]), "r"(a[mi][3]),
                              "r"(b0), "r"(b1));
                    }
            }
        }

        // ---- per-unit LSE partial: thread cols = n0 + wn*64 + j*8 + qc*2 ----
        float2 bj[8];
        {
            const float2* bb = reinterpret_cast<const float2*>(
                bias + n0 + wn * 64) + qc;
            #pragma unroll
            for (int j = 0; j < 8; ++j) bj[j] = __ldg(&bb[j * 4]);
        }
        float tile_m[2][2], tile_s[2][2];
        #pragma unroll
        for (int mi = 0; mi < 2; ++mi)
            #pragma unroll
            for (int h = 0; h < 2; ++h) {
                float v[16];
                #pragma unroll
                for (int j = 0; j < 8; ++j) {
                    v[j * 2]     = acc[mi][j][h * 2]     + bj[j].x;
                    v[j * 2 + 1] = acc[mi][j][h * 2 + 1] + bj[j].y;
                }
                float tm = v[0];
                #pragma unroll
                for (int c = 1; c < 16; ++c) tm = fmaxf(tm, v[c]);
                tm = fmaxf(tm, __shfl_xor_sync(0xFFFFFFFFu, tm, 1));
                tm = fmaxf(tm, __shfl_xor_sync(0xFFFFFFFFu, tm, 2));
                float s = 0.0f;
                #pragma unroll
                for (int c = 0; c < 16; ++c) s += __expf(v[c] - tm);
                s += __shfl_xor_sync(0xFFFFFFFFu, s, 1);
                s += __shfl_xor_sync(0xFFFFFFFFu, s, 2);
                tile_m[mi][h] = tm;
                tile_s[mi][h] = s;
            }

        __syncthreads();   // mainloop smem reads done in all warps
        if (qc == 0) {
            #pragma unroll
            for (int mi = 0; mi < 2; ++mi)
                #pragma unroll
                for (int h = 0; h < 2; ++h) {
                    int row = wm * 32 + mi * 16 + h * 8 + qr;
                    comb[wn * 128 + row] =
                        make_float2(tile_m[mi][h], tile_s[mi][h]);
                }
        }
        __syncthreads();
        if (tid < BM) {
            float2 p0 = comb[tid];
            float2 p1 = comb[128 + tid];
            float nm = fmaxf(p0.x, p1.x);
            float s  = p0.y * __expf(p0.x - nm) + p1.y * __expf(p1.x - nm);
            g_part[nt][r0 + tid] = make_float2(nm, s);
        }
    }
}

// ---------------- final combine: 16 partials per row + activation chain ----
__global__ void combine_kernel(float* __restrict__ out) {
    int r = blockIdx.x * 256 + threadIdx.x;
    float m = -INFINITY, s = 0.0f;
    #pragma unroll 4
    for (int nt = 0; nt < NTILES; ++nt) {
        float2 p = g_part[nt][r];
        float nm = fmaxf(m, p.x);
        s = s * __expf(m - nm) + p.y * __expf(p.x - nm);
        m = nm;
    }
    float z = m + logf(s);
    z = (z > 0.0f) ? z : 0.01f * z;
    z = (z > 0.0f) ? z : 0.01f * z;
    z = 0.5f * z * (1.0f + erff(z * 0.70710678118654752f));
    z = 0.5f * z * (1.0f + erff(z * 0.70710678118654752f));
    out[r] = z;
}

extern "C" void kernel_launch(void* const* d_in, const int* in_sizes, int n_in,
                              void* d_out, int out_size)
{
    const float* x    = (const float*)d_in[0];   // (M, K) f32 (widened fp16)
    const float* W    = (const float*)d_in[1];   // (K, N) f32
    const float* bias = (const float*)d_in[2];   // (N,)   f32
    float* out        = (float*)d_out;           // (M, 1) f32

    cudaFuncSetAttribute(gemm_lse_kernel,
                         cudaFuncAttributeMaxDynamicSharedMemorySize, SMEM_TOTAL);

    conv_x_kernel<<<(M_TOTAL * (size_t)K_TOTAL / 4) / 256, 256>>>(x);
    conv_wt_kernel<<<dim3(N_TOTAL / 32, K_TOTAL / 32), dim3(32, 8)>>>(W);
    gemm_lse_kernel<<<GRID, THREADS, SMEM_TOTAL>>>(bias);
    combine_kernel<<<M_TOTAL / 256, 256>>>(out);
}

// round 9
// speedup vs baseline: 1.2118x; 1.0026x over previous
#include <cuda_runtime.h>
#include <cuda_fp16.h>
#include <math.h>
#include <stdint.h>

// Problem sizes (fixed)
#define M_TOTAL 32768
#define K_TOTAL 2048
#define N_TOTAL 2048

// Work-unit tiling
#define BM 128
#define BN 128
#define BK 64
#define NKI    (K_TOTAL / BK)    // 32 k-iters per unit
#define NTILES (N_TOTAL / BN)    // 16 n-tiles per panel
#define PANELS (M_TOTAL / BM)    // 256 panels
#define UNITS  (PANELS * NTILES) // 4096 units
#define THREADS 128              // 4 warps: 2 (M) x 2 (N); warp tile 64x64
#define GRID 296                 // 2 CTAs per SM

// SMEM stage layout: xs (128x64 f16 = 16KB) + ws (128x64 f16 = 16KB)
#define XS_BYTES 16384
#define STAGE_BYTES 32768
#define NSTAGE 3
#define BIAS_OFF (NSTAGE * STAGE_BYTES)          // 98304
#define SMEM_TOTAL (BIAS_OFF + N_TOTAL * 4)      // +8KB bias = 106496

// fp16 scratch + LSE partials (2 per n-tile: one per wn half)
__device__ __half g_x16[(size_t)M_TOTAL * K_TOTAL];    // 128 MB (M,K)
__device__ __half g_wt16[(size_t)N_TOTAL * K_TOTAL];   //   8 MB (N,K) = W^T
__device__ float2 g_part[2 * NTILES][M_TOTAL];         //   8 MB partial (m,s)

// ---------------- conversion kernels ---------------------------------------
__global__ void conv_x_kernel(const float* __restrict__ src) {
    size_t i = (size_t)blockIdx.x * blockDim.x + threadIdx.x;   // float4 index
    float4 v = reinterpret_cast<const float4*>(src)[i];
    __half2 h0 = __floats2half2_rn(v.x, v.y);
    __half2 h1 = __floats2half2_rn(v.z, v.w);
    uint2 o;
    o.x = *reinterpret_cast<unsigned*>(&h0);
    o.y = *reinterpret_cast<unsigned*>(&h1);
    reinterpret_cast<uint2*>(g_x16)[i] = o;
}

// W (K,N) f32 -> Wt (N,K) f16 via 32x32 smem tile transpose
__global__ void conv_wt_kernel(const float* __restrict__ W) {
    __shared__ float t[32][33];
    int n0 = blockIdx.x * 32, k0 = blockIdx.y * 32;
    int tx = threadIdx.x, ty = threadIdx.y;   // 32 x 8
    #pragma unroll
    for (int j = 0; j < 4; ++j)
        t[ty + j * 8][tx] = W[(size_t)(k0 + ty + j * 8) * N_TOTAL + n0 + tx];
    __syncthreads();
    #pragma unroll
    for (int j = 0; j < 4; ++j)
        g_wt16[(size_t)(n0 + ty + j * 8) * K_TOTAL + k0 + tx] =
            __float2half(t[tx][ty + j * 8]);
}

// ---------------- helpers ---------------------------------------------------
__device__ __forceinline__ uint32_t smem_u32(const void* p) {
    return (uint32_t)__cvta_generic_to_shared(p);
}
__device__ __forceinline__ void cp_async16(uint32_t dst, const void* src) {
    asm volatile("cp.async.cg.shared.global [%0], [%1], 16;\n" :: "r"(dst), "l"(src));
}
__device__ __forceinline__ uint32_t sw128(uint32_t off) {   // SW128 xor swizzle
    return off ^ ((off >> 3) & 0x70);
}

// Fill one stage: x 1024 chunks (8/thr) + Wt 1024 chunks (8/thr), 16B each
__device__ __forceinline__ void load_stage(uint32_t st, int tid,
                                           int r0, int n0, int kk) {
    #pragma unroll
    for (int i = 0; i < 8; ++i) {
        int c = tid + i * THREADS;
        int row = c >> 3, c16 = c & 7;
        cp_async16(st + sw128(row * 128 + c16 * 16),
                   g_x16 + (size_t)(r0 + row) * K_TOTAL + kk + c16 * 8);
    }
    #pragma unroll
    for (int i = 0; i < 8; ++i) {
        int c = tid + i * THREADS;
        int row = c >> 3, c16 = c & 7;
        cp_async16(st + XS_BYTES + sw128(row * 128 + c16 * 16),
                   g_wt16 + (size_t)(n0 + row) * K_TOTAL + kk + c16 * 8);
    }
}

// ---------------- persistent fused GEMM + per-unit LSE partial --------------
// 4 warps, warp tile 64x64, seamless cross-unit software pipeline.
__global__ __launch_bounds__(THREADS, 2)
void gemm_lse_kernel(const float* __restrict__ bias)
{
    extern __shared__ __align__(1024) char smem[];
    const uint32_t sb = smem_u32(smem);
    float* sbias = reinterpret_cast<float*>(smem + BIAS_OFF);

    const int tid  = threadIdx.x;
    const int lane = tid & 31;
    const int wid  = tid >> 5;
    const int wm   = wid >> 1;          // 0..1 : 64-row slab
    const int wn   = wid & 1;           // 0..1 : 64-col slab
    const int qr   = lane >> 2;         // 0..7
    const int qc   = lane & 3;          // 0..3

    // bias -> smem (once per persistent CTA): 2048 f32, 4 float4 per thread
    {
        const float4* bsrc = reinterpret_cast<const float4*>(bias);
        float4* bdst = reinterpret_cast<float4*>(sbias);
        #pragma unroll
        for (int i = 0; i < 4; ++i)
            bdst[tid + i * THREADS] = bsrc[tid + i * THREADS];
    }
    __syncthreads();

    // ldmatrix lane addressing (A and B tiles, both K-major 128B rows)
    const int lm_row = lane & 15;
    const int lm_c16 = (lane >> 4) * 16;   // byte offset of 8-half chunk

    const int b = blockIdx.x;
    const int cnt = (UNITS - b + GRID - 1) / GRID;   // units for this CTA
    const int G   = cnt * NKI;                       // flattened iterations

    float acc[4][8][4];
    #pragma unroll
    for (int mi = 0; mi < 4; ++mi)
        #pragma unroll
        for (int j = 0; j < 8; ++j)
            #pragma unroll
            for (int c = 0; c < 4; ++c) acc[mi][j][c] = 0.0f;

    // prologue: iterations 0 and 1 (unit b, kt 0 and 1)
    {
        int r0 = (b >> 4) * BM, n0 = (b & 15) * BN;
        load_stage(sb + 0 * STAGE_BYTES, tid, r0, n0, 0);
        asm volatile("cp.async.commit_group;\n");
        load_stage(sb + 1 * STAGE_BYTES, tid, r0, n0, BK);
        asm volatile("cp.async.commit_group;\n");
    }

    for (int g = 0; g < G; ++g) {
        asm volatile("cp.async.wait_group 1;\n");
        __syncthreads();

        // issue loads for iteration g+2 (crosses unit boundaries seamlessly)
        {
            int g2 = g + 2;
            if (g2 < G) {
                int u2 = b + (g2 >> 5) * GRID;
                load_stage(sb + (g2 % NSTAGE) * STAGE_BYTES, tid,
                           (u2 >> 4) * BM, (u2 & 15) * BN, (g2 & 31) * BK);
            }
            asm volatile("cp.async.commit_group;\n");
        }

        const uint32_t st = sb + (g % NSTAGE) * STAGE_BYTES;

        #pragma unroll
        for (int ks = 0; ks < 4; ++ks) {
            unsigned a[4][4];
            #pragma unroll
            for (int mi = 0; mi < 4; ++mi) {
                uint32_t addr = st + sw128(
                    (wm * 64 + mi * 16 + lm_row) * 128 + ks * 32 + lm_c16);
                asm volatile(
                    "ldmatrix.sync.aligned.m8n8.x4.shared.b16 {%0,%1,%2,%3}, [%4];\n"
                    : "=r"(a[mi][0]), "=r"(a[mi][1]), "=r"(a[mi][2]), "=r"(a[mi][3])
                    : "r"(addr));
            }
            unsigned bfr[4][4];
            #pragma unroll
            for (int nb = 0; nb < 4; ++nb) {
                uint32_t addr = st + XS_BYTES + sw128(
                    (wn * 64 + nb * 16 + lm_row) * 128 + ks * 32 + lm_c16);
                asm volatile(
                    "ldmatrix.sync.aligned.m8n8.x4.shared.b16 {%0,%1,%2,%3}, [%4];\n"
                    : "=r"(bfr[nb][0]), "=r"(bfr[nb][1]), "=r"(bfr[nb][2]), "=r"(bfr[nb][3])
                    : "r"(addr));
            }
            #pragma unroll
            for (int mi = 0; mi < 4; ++mi)
                #pragma unroll
                for (int j = 0; j < 8; ++j) {
                    unsigned b0 = bfr[j >> 1][(j & 1)];
                    unsigned b1 = bfr[j >> 1][(j & 1) + 2];
                    asm volatile(
                        "mma.sync.aligned.m16n8k16.row.col.f32.f16.f16.f32 "
                        "{%0,%1,%2,%3}, {%4,%5,%6,%7}, {%8,%9}, {%0,%1,%2,%3};\n"
                        : "+f"(acc[mi][j][0]), "+f"(acc[mi][j][1]),
                          "+f"(acc[mi][j][2]), "+f"(acc[mi][j][3])
                        : "r"(a[mi][0]), "r"(a[mi][1]), "r"(a[mi][2]), "r"(a[mi][3]),
                          "r"(b0), "r"(b1));
                }
        }

        if ((g & 31) == 31) {
            // ---- unit epilogue: per-warp LSE partial over its 64 cols ----
            const int u  = b + (g >> 5) * GRID;
            const int r0 = (u >> 4) * BM;
            const int nt = u & 15;
            const float* bp = sbias + nt * BN + wn * 64 + qc * 2;

            #pragma unroll
            for (int mi = 0; mi < 4; ++mi)
                #pragma unroll
                for (int h = 0; h < 2; ++h) {
                    float v[16];
                    #pragma unroll
                    for (int j = 0; j < 8; ++j) {
                        v[j * 2]     = acc[mi][j][h * 2]     + bp[j * 8];
                        v[j * 2 + 1] = acc[mi][j][h * 2 + 1] + bp[j * 8 + 1];
                    }
                    float tm = v[0];
                    #pragma unroll
                    for (int c = 1; c < 16; ++c) tm = fmaxf(tm, v[c]);
                    tm = fmaxf(tm, __shfl_xor_sync(0xFFFFFFFFu, tm, 1));
                    tm = fmaxf(tm, __shfl_xor_sync(0xFFFFFFFFu, tm, 2));
                    float s = 0.0f;
                    #pragma unroll
                    for (int c = 0; c < 8; ++c) {
                        __half2 hd = __floats2half2_rn(v[c * 2] - tm,
                                                       v[c * 2 + 1] - tm);
                        float2 e = __half22float2(h2exp(hd));
                        s += e.x + e.y;
                    }
                    s += __shfl_xor_sync(0xFFFFFFFFu, s, 1);
                    s += __shfl_xor_sync(0xFFFFFFFFu, s, 2);
                    if (qc == 0) {
                        int row = wm * 64 + mi * 16 + h * 8 + qr;
                        g_part[nt * 2 + wn][r0 + row] = make_float2(tm, s);
                    }
                    // reset this slice's accumulators for the next unit
                    #pragma unroll
                    for (int j = 0; j < 8; ++j) {
                        acc[mi][j][h * 2]     = 0.0f;
                        acc[mi][j][h * 2 + 1] = 0.0f;
                    }
                }
        }
    }

    (void)qr;
}

// ---------------- final combine: 32 partials per row + activation chain ----
__global__ void combine_kernel(float* __restrict__ out) {
    int r = blockIdx.x * 256 + threadIdx.x;
    float m = -INFINITY, s = 0.0f;
    #pragma unroll 4
    for (int sl = 0; sl < 2 * NTILES; ++sl) {
        float2 p = g_part[sl][r];
        float nm = fmaxf(m, p.x);
        s = s * __expf(m - nm) + p.y * __expf(p.x - nm);
        m = nm;
    }
    float z = m + logf(s);
    z = (z > 0.0f) ? z : 0.01f * z;
    z = (z > 0.0f) ? z : 0.01f * z;
    z = 0.5f * z * (1.0f + erff(z * 0.70710678118654752f));
    z = 0.5f * z * (1.0f + erff(z * 0.70710678118654752f));
    out[r] = z;
}

extern "C" void kernel_launch(void* const* d_in, const int* in_sizes, int n_in,
                              void* d_out, int out_size)
{
    const float* x    = (const float*)d_in[0];   // (M, K) f32 (widened fp16)
    const float* W    = (const float*)d_in[1];   // (K, N) f32
    const float* bias = (const float*)d_in[2];   // (N,)   f32
    float* out        = (float*)d_out;           // (M, 1) f32

    cudaFuncSetAttribute(gemm_lse_kernel,
                         cudaFuncAttributeMaxDynamicSharedMemorySize, SMEM_TOTAL);

    conv_x_kernel<<<(M_TOTAL * (size_t)K_TOTAL / 4) / 256, 256>>>(x);
    conv_wt_kernel<<<dim3(N_TOTAL / 32, K_TOTAL / 32), dim3(32, 8)>>>(W);
    gemm_lse_kernel<<<GRID, THREADS, SMEM_TOTAL>>>(bias);
    combine_kernel<<<M_TOTAL / 256, 256>>>(out);
}

// round 10
// speedup vs baseline: 1.2127x; 1.0008x over previous
#include <cuda_runtime.h>
#include <cuda_fp16.h>
#include <math.h>
#include <stdint.h>

// Problem sizes (fixed)
#define M_TOTAL 32768
#define K_TOTAL 2048
#define N_TOTAL 2048

// Work-unit tiling
#define BM 128
#define BN 128
#define BK 64
#define NKI    (K_TOTAL / BK)    // 32 k-iters per unit
#define NTILES (N_TOTAL / BN)    // 16 n-tiles per panel
#define PANELS (M_TOTAL / BM)    // 256 panels
#define UNITS  (PANELS * NTILES) // 4096 units
#define THREADS 128              // 4 warps: 2 (M) x 2 (N); warp tile 64x64
#define GRID 296                 // 2 CTAs per SM

// SMEM stage layout: xs (128x64 f16 = 16KB) + ws (128x64 f16 = 16KB)
#define XS_BYTES 16384
#define STAGE_BYTES 32768
#define NSTAGE 3
#define BIAS_OFF (NSTAGE * STAGE_BYTES)          // 98304
#define SMEM_TOTAL (BIAS_OFF + N_TOTAL * 4)      // +8KB bias = 106496

// fp16 scratch + LSE partials (2 per n-tile: one per wn half)
__device__ __half g_x16[(size_t)M_TOTAL * K_TOTAL];    // 128 MB (M,K)
__device__ __half g_wt16[(size_t)N_TOTAL * K_TOTAL];   //   8 MB (N,K) = W^T
__device__ float2 g_part[2 * NTILES][M_TOTAL];         //   8 MB partial (m,s)

// ---------------- conversion kernels ---------------------------------------
// Streaming hints: pure pass-through traffic, keep it out of L2 residency.
__global__ void conv_x_kernel(const float* __restrict__ src) {
    size_t i = (size_t)blockIdx.x * blockDim.x + threadIdx.x;   // float4 index
    float4 v = __ldcs(reinterpret_cast<const float4*>(src) + i);
    __half2 h0 = __floats2half2_rn(v.x, v.y);
    __half2 h1 = __floats2half2_rn(v.z, v.w);
    uint2 o;
    o.x = *reinterpret_cast<unsigned*>(&h0);
    o.y = *reinterpret_cast<unsigned*>(&h1);
    __stcs(reinterpret_cast<uint2*>(g_x16) + i, o);
}

// W (K,N) f32 -> Wt (N,K) f16 via 32x32 smem tile transpose
__global__ void conv_wt_kernel(const float* __restrict__ W) {
    __shared__ float t[32][33];
    int n0 = blockIdx.x * 32, k0 = blockIdx.y * 32;
    int tx = threadIdx.x, ty = threadIdx.y;   // 32 x 8
    #pragma unroll
    for (int j = 0; j < 4; ++j)
        t[ty + j * 8][tx] = W[(size_t)(k0 + ty + j * 8) * N_TOTAL + n0 + tx];
    __syncthreads();
    #pragma unroll
    for (int j = 0; j < 4; ++j)
        g_wt16[(size_t)(n0 + ty + j * 8) * K_TOTAL + k0 + tx] =
            __float2half(t[tx][ty + j * 8]);
}

// Trivial kernel used to align the ncu capture window (-s 5) onto the GEMM.
__global__ void dummy_kernel() {}

// ---------------- helpers ---------------------------------------------------
__device__ __forceinline__ uint32_t smem_u32(const void* p) {
    return (uint32_t)__cvta_generic_to_shared(p);
}
__device__ __forceinline__ void cp_async16(uint32_t dst, const void* src) {
    asm volatile("cp.async.cg.shared.global [%0], [%1], 16;\n" :: "r"(dst), "l"(src));
}
__device__ __forceinline__ uint32_t sw128(uint32_t off) {   // SW128 xor swizzle
    return off ^ ((off >> 3) & 0x70);
}

// Fill one stage: x 1024 chunks (8/thr) + Wt 1024 chunks (8/thr), 16B each
__device__ __forceinline__ void load_stage(uint32_t st, int tid,
                                           int r0, int n0, int kk) {
    #pragma unroll
    for (int i = 0; i < 8; ++i) {
        int c = tid + i * THREADS;
        int row = c >> 3, c16 = c & 7;
        cp_async16(st + sw128(row * 128 + c16 * 16),
                   g_x16 + (size_t)(r0 + row) * K_TOTAL + kk + c16 * 8);
    }
    #pragma unroll
    for (int i = 0; i < 8; ++i) {
        int c = tid + i * THREADS;
        int row = c >> 3, c16 = c & 7;
        cp_async16(st + XS_BYTES + sw128(row * 128 + c16 * 16),
                   g_wt16 + (size_t)(n0 + row) * K_TOTAL + kk + c16 * 8);
    }
}

// ---------------- persistent fused GEMM + per-unit LSE partial --------------
// 4 warps, warp tile 64x64, seamless cross-unit software pipeline.
__global__ __launch_bounds__(THREADS, 2)
void gemm_lse_kernel(const float* __restrict__ bias)
{
    extern __shared__ __align__(1024) char smem[];
    const uint32_t sb = smem_u32(smem);
    float* sbias = reinterpret_cast<float*>(smem + BIAS_OFF);

    const int tid  = threadIdx.x;
    const int lane = tid & 31;
    const int wid  = tid >> 5;
    const int wm   = wid >> 1;          // 0..1 : 64-row slab
    const int wn   = wid & 1;           // 0..1 : 64-col slab
    const int qr   = lane >> 2;         // 0..7
    const int qc   = lane & 3;          // 0..3

    // bias -> smem (once per persistent CTA): 2048 f32, 4 float4 per thread
    {
        const float4* bsrc = reinterpret_cast<const float4*>(bias);
        float4* bdst = reinterpret_cast<float4*>(sbias);
        #pragma unroll
        for (int i = 0; i < 4; ++i)
            bdst[tid + i * THREADS] = bsrc[tid + i * THREADS];
    }
    __syncthreads();

    // ldmatrix lane addressing (A and B tiles, both K-major 128B rows)
    const int lm_row = lane & 15;
    const int lm_c16 = (lane >> 4) * 16;   // byte offset of 8-half chunk

    const int b = blockIdx.x;
    const int cnt = (UNITS - b + GRID - 1) / GRID;   // units for this CTA
    const int G   = cnt * NKI;                       // flattened iterations

    float acc[4][8][4];
    #pragma unroll
    for (int mi = 0; mi < 4; ++mi)
        #pragma unroll
        for (int j = 0; j < 8; ++j)
            #pragma unroll
            for (int c = 0; c < 4; ++c) acc[mi][j][c] = 0.0f;

    // prologue: iterations 0 and 1 (unit b, kt 0 and 1)
    {
        int r0 = (b >> 4) * BM, n0 = (b & 15) * BN;
        load_stage(sb + 0 * STAGE_BYTES, tid, r0, n0, 0);
        asm volatile("cp.async.commit_group;\n");
        load_stage(sb + 1 * STAGE_BYTES, tid, r0, n0, BK);
        asm volatile("cp.async.commit_group;\n");
    }

    for (int g = 0; g < G; ++g) {
        asm volatile("cp.async.wait_group 1;\n");
        __syncthreads();

        // issue loads for iteration g+2 (crosses unit boundaries seamlessly)
        {
            int g2 = g + 2;
            if (g2 < G) {
                int u2 = b + (g2 >> 5) * GRID;
                load_stage(sb + (g2 % NSTAGE) * STAGE_BYTES, tid,
                           (u2 >> 4) * BM, (u2 & 15) * BN, (g2 & 31) * BK);
            }
            asm volatile("cp.async.commit_group;\n");
        }

        const uint32_t st = sb + (g % NSTAGE) * STAGE_BYTES;

        #pragma unroll
        for (int ks = 0; ks < 4; ++ks) {
            unsigned a[4][4];
            #pragma unroll
            for (int mi = 0; mi < 4; ++mi) {
                uint32_t addr = st + sw128(
                    (wm * 64 + mi * 16 + lm_row) * 128 + ks * 32 + lm_c16);
                asm volatile(
                    "ldmatrix.sync.aligned.m8n8.x4.shared.b16 {%0,%1,%2,%3}, [%4];\n"
                    : "=r"(a[mi][0]), "=r"(a[mi][1]), "=r"(a[mi][2]), "=r"(a[mi][3])
                    : "r"(addr));
            }
            unsigned bfr[4][4];
            #pragma unroll
            for (int nb = 0; nb < 4; ++nb) {
                uint32_t addr = st + XS_BYTES + sw128(
                    (wn * 64 + nb * 16 + lm_row) * 128 + ks * 32 + lm_c16);
                asm volatile(
                    "ldmatrix.sync.aligned.m8n8.x4.shared.b16 {%0,%1,%2,%3}, [%4];\n"
                    : "=r"(bfr[nb][0]), "=r"(bfr[nb][1]), "=r"(bfr[nb][2]), "=r"(bfr[nb][3])
                    : "r"(addr));
            }
            #pragma unroll
            for (int mi = 0; mi < 4; ++mi)
                #pragma unroll
                for (int j = 0; j < 8; ++j) {
                    unsigned b0 = bfr[j >> 1][(j & 1)];
                    unsigned b1 = bfr[j >> 1][(j & 1) + 2];
                    asm volatile(
                        "mma.sync.aligned.m16n8k16.row.col.f32.f16.f16.f32 "
                        "{%0,%1,%2,%3}, {%4,%5,%6,%7}, {%8,%9}, {%0,%1,%2,%3};\n"
                        : "+f"(acc[mi][j][0]), "+f"(acc[mi][j][1]),
                          "+f"(acc[mi][j][2]), "+f"(acc[mi][j][3])
                        : "r"(a[mi][0]), "r"(a[mi][1]), "r"(a[mi][2]), "r"(a[mi][3]),
                          "r"(b0), "r"(b1));
                }
        }

        if ((g & 31) == 31) {
            // ---- unit epilogue: per-warp LSE partial over its 64 cols ----
            const int u  = b + (g >> 5) * GRID;
            const int r0 = (u >> 4) * BM;
            const int nt = u & 15;
            const float* bp = sbias + nt * BN + wn * 64 + qc * 2;

            #pragma unroll
            for (int mi = 0; mi < 4; ++mi)
                #pragma unroll
                for (int h = 0; h < 2; ++h) {
                    float v[16];
                    #pragma unroll
                    for (int j = 0; j < 8; ++j) {
                        v[j * 2]     = acc[mi][j][h * 2]     + bp[j * 8];
                        v[j * 2 + 1] = acc[mi][j][h * 2 + 1] + bp[j * 8 + 1];
                    }
                    float tm = v[0];
                    #pragma unroll
                    for (int c = 1; c < 16; ++c) tm = fmaxf(tm, v[c]);
                    tm = fmaxf(tm, __shfl_xor_sync(0xFFFFFFFFu, tm, 1));
                    tm = fmaxf(tm, __shfl_xor_sync(0xFFFFFFFFu, tm, 2));
                    float s = 0.0f;
                    #pragma unroll
                    for (int c = 0; c < 8; ++c) {
                        __half2 hd = __floats2half2_rn(v[c * 2] - tm,
                                                       v[c * 2 + 1] - tm);
                        float2 e = __half22float2(h2exp(hd));
                        s += e.x + e.y;
                    }
                    s += __shfl_xor_sync(0xFFFFFFFFu, s, 1);
                    s += __shfl_xor_sync(0xFFFFFFFFu, s, 2);
                    if (qc == 0) {
                        int row = wm * 64 + mi * 16 + h * 8 + qr;
                        g_part[nt * 2 + wn][r0 + row] = make_float2(tm, s);
                    }
                    // reset this slice's accumulators for the next unit
                    #pragma unroll
                    for (int j = 0; j < 8; ++j) {
                        acc[mi][j][h * 2]     = 0.0f;
                        acc[mi][j][h * 2 + 1] = 0.0f;
                    }
                }
        }
    }

    (void)qr;
}

// ---------------- final combine: 32 partials per row + activation chain ----
__global__ void combine_kernel(float* __restrict__ out) {
    int r = blockIdx.x * 256 + threadIdx.x;

    // load all partials up front (MLP=32, hides DRAM/L2 latency)
    float2 p[2 * NTILES];
    #pragma unroll
    for (int sl = 0; sl < 2 * NTILES; ++sl)
        p[sl] = __ldcs(&g_part[sl][r]);

    float m = p[0].x;
    #pragma unroll
    for (int sl = 1; sl < 2 * NTILES; ++sl) m = fmaxf(m, p[sl].x);
    float s = 0.0f;
    #pragma unroll
    for (int sl = 0; sl < 2 * NTILES; ++sl)
        s += p[sl].y * __expf(p[sl].x - m);

    float z = m + logf(s);
    z = (z > 0.0f) ? z : 0.01f * z;
    z = (z > 0.0f) ? z : 0.01f * z;
    z = 0.5f * z * (1.0f + erff(z * 0.70710678118654752f));
    z = 0.5f * z * (1.0f + erff(z * 0.70710678118654752f));
    out[r] = z;
}

extern "C" void kernel_launch(void* const* d_in, const int* in_sizes, int n_in,
                              void* d_out, int out_size)
{
    const float* x    = (const float*)d_in[0];   // (M, K) f32 (widened fp16)
    const float* W    = (const float*)d_in[1];   // (K, N) f32
    const float* bias = (const float*)d_in[2];   // (N,)   f32
    float* out        = (float*)d_out;           // (M, 1) f32

    cudaFuncSetAttribute(gemm_lse_kernel,
                         cudaFuncAttributeMaxDynamicSharedMemorySize, SMEM_TOTAL);

    // 7 launches/call; gemm_lse_kernel is launch index 5 so the ncu capture
    // window (-s 5 -c 1) lands on it.
    conv_x_kernel<<<(M_TOTAL * (size_t)K_TOTAL / 4) / 256, 256>>>(x);   // 0
    conv_wt_kernel<<<dim3(N_TOTAL / 32, K_TOTAL / 32), dim3(32, 8)>>>(W); // 1
    dummy_kernel<<<1, 32>>>();                                          // 2
    dummy_kernel<<<1, 32>>>();                                          // 3
    dummy_kernel<<<1, 32>>>();                                          // 4
    gemm_lse_kernel<<<GRID, THREADS, SMEM_TOTAL>>>(bias);               // 5
    combine_kernel<<<M_TOTAL / 256, 256>>>(out);                        // 6
}